// round 6
// baseline (speedup 1.0000x reference)
#include <cuda_runtime.h>
#include <cuda_bf16.h>
#include <cuda_fp16.h>
#include <math.h>
#include <stdint.h>

#define Bb 2
#define Dd 256
#define Nn 8192
#define CIc 128
#define Mm 4096
#define LOG2E 1.4426950408889634f

// smem strides (halfwords)
#define WS2 40    // proj W tile [c][d-chunk]     (20 words mod 32 -> distinct)
#define FS2 136   // proj f tile [d][n]           (68 words mod 32 = 4)
#define THH 136   // theta [q][c] fp16
#define PHH 136   // phi   [k][c] fp16
#define GH2 136   // g     [m][c] bf16
#define WWH 136   // wconv tiles [row][c] fp16

// -------- scratch (static device globals; no runtime allocation) --------
__device__ __half         d_thh[Bb*Nn*CIc];    // theta*log2e, (B, N, CI) fp16
__device__ __half         d_phT[Bb*Mm*CIc];    // pooled phi,  (B, M, CI) fp16
__device__ __nv_bfloat16  d_gbf[Bb*Mm*CIc];    // pooled g,    (B, M, CI) bf16
__device__ __half         d_yh[Bb*Nn*CIc];     // attention out, (B, N, CI) fp16
__device__ float          d_Wy[Bb*Dd*Nn];      // W conv output (B, D, N)
__device__ double         d_sum[Dd*128];       // BN partials: [d][nblk*2+b]
__device__ double         d_sq[Dd*128];

// ---------------- helpers ----------------
__device__ __forceinline__ float ex2f(float x) {
    float y;
    asm("ex2.approx.f32 %0, %1;" : "=f"(y) : "f"(x));
    return y;
}
__device__ __forceinline__ void mma_f16(float* d, const uint32_t* a,
                                        uint32_t b0, uint32_t b1) {
    asm volatile(
        "mma.sync.aligned.m16n8k16.row.col.f32.f16.f16.f32 "
        "{%0,%1,%2,%3},{%4,%5,%6,%7},{%8,%9},{%0,%1,%2,%3};"
        : "+f"(d[0]), "+f"(d[1]), "+f"(d[2]), "+f"(d[3])
        : "r"(a[0]), "r"(a[1]), "r"(a[2]), "r"(a[3]), "r"(b0), "r"(b1));
}
__device__ __forceinline__ void mma_bf16(float* d, const uint32_t* a,
                                         uint32_t b0, uint32_t b1) {
    asm volatile(
        "mma.sync.aligned.m16n8k16.row.col.f32.bf16.bf16.f32 "
        "{%0,%1,%2,%3},{%4,%5,%6,%7},{%8,%9},{%0,%1,%2,%3};"
        : "+f"(d[0]), "+f"(d[1]), "+f"(d[2]), "+f"(d[3])
        : "r"(a[0]), "r"(a[1]), "r"(a[2]), "r"(a[3]), "r"(b0), "r"(b1));
}
__device__ __forceinline__ void ldsm4(uint32_t& r0, uint32_t& r1,
                                      uint32_t& r2, uint32_t& r3, uint32_t a) {
    asm volatile("ldmatrix.sync.aligned.m8n8.x4.shared.b16 {%0,%1,%2,%3}, [%4];"
                 : "=r"(r0), "=r"(r1), "=r"(r2), "=r"(r3) : "r"(a));
}
__device__ __forceinline__ void ldsm4t(uint32_t& r0, uint32_t& r1,
                                       uint32_t& r2, uint32_t& r3, uint32_t a) {
    asm volatile("ldmatrix.sync.aligned.m8n8.x4.trans.shared.b16 {%0,%1,%2,%3}, [%4];"
                 : "=r"(r0), "=r"(r1), "=r"(r2), "=r"(r3) : "r"(a));
}
__device__ __forceinline__ void cp16(uint32_t dst, const void* src) {
    asm volatile("cp.async.cg.shared.global [%0], [%1], 16;\n"
                 :: "r"(dst), "l"(src));
}
__device__ __forceinline__ uint32_t packbf(float a, float b) {
    __nv_bfloat162 p = __floats2bfloat162_rn(a, b);
    return *reinterpret_cast<uint32_t*>(&p);
}
__device__ __forceinline__ uint32_t shflx4(uint32_t v) {
    return __shfl_xor_sync(0xffffffffu, v, 4);
}

// ============================================================================
// Kernel 1: three 1x1-conv projections, fp16 mma, outputs [n][c]-oriented.
// out[n][c] = sum_d f^T[n][d] W^T[d][c]:
//   A = f^T via ldmatrix.trans on f tile stored [d][n] (natural layout)
//   B = W    via ldmatrix on W tile stored [c][d]      (natural layout)
// zi=0: theta -> fp16 (B,N,CI), pre-scaled by log2e
// zi=1: g     -> maxpool2 (shfl) -> bf16 (B,M,CI)
// zi=2: phi   -> maxpool2 (shfl) -> fp16 (B,M,CI)
// Warp tile: 32n x 64c. CTA: 128n x 128c, K=256.
// ============================================================================
__global__ __launch_bounds__(256) void proj_tc(
    const float* __restrict__ f,
    const float* __restrict__ gw, const float* __restrict__ gb,
    const float* __restrict__ tw, const float* __restrict__ tb,
    const float* __restrict__ pw, const float* __restrict__ pb)
{
    const int zi = blockIdx.y;
    const float* W  = (zi == 0) ? tw : (zi == 1) ? gw : pw;
    const float* bs = (zi == 0) ? tb : (zi == 1) ? gb : pb;

    const int b    = blockIdx.z;
    const int n0   = blockIdx.x * 128;
    const int tid  = threadIdx.x;
    const int warp = tid >> 5;
    const int lane = tid & 31;
    const int grp  = lane >> 2;
    const int tig  = lane & 3;
    const int Qn   = (warp & 3) * 32;   // n offset within CTA
    const int Cw   = (warp >> 2) * 64;  // c offset
    const int lrow = ((lane >> 4) << 3) + (lane & 7);
    const int lcol = ((lane >> 3) & 1) * 8;

    __shared__ __half w_sm[128 * WS2];
    __shared__ __half f_sm[32 * FS2];
    const uint32_t wsb = (uint32_t)__cvta_generic_to_shared(w_sm);
    const uint32_t fsb = (uint32_t)__cvta_generic_to_shared(f_sm);

    float acc[2][8][4];
    #pragma unroll
    for (int mt = 0; mt < 2; mt++)
        #pragma unroll
        for (int nt = 0; nt < 8; nt++)
            #pragma unroll
            for (int r = 0; r < 4; r++) acc[mt][nt][r] = 0.f;

    const float* fb = f + (size_t)b * Dd * Nn;

    for (int d0 = 0; d0 < Dd; d0 += 32) {
        __syncthreads();
        {   // W chunk: 128c x 32d, fp32 -> fp16
            int c = tid >> 1, dl = (tid & 1) * 16;
            const float* wp = &W[c * Dd + d0 + dl];
            #pragma unroll
            for (int j = 0; j < 4; j++) {
                float4 v = *(const float4*)&wp[j * 4];
                *(__half2*)&w_sm[c * WS2 + dl + j * 4    ] = __floats2half2_rn(v.x, v.y);
                *(__half2*)&w_sm[c * WS2 + dl + j * 4 + 2] = __floats2half2_rn(v.z, v.w);
            }
        }
        {   // f chunk: 32d x 128n, fp32 -> fp16
            int dd = tid >> 3, nf = (tid & 7) * 16;
            const float* fp = &fb[(size_t)(d0 + dd) * Nn + n0 + nf];
            #pragma unroll
            for (int j = 0; j < 4; j++) {
                float4 v = *(const float4*)&fp[j * 4];
                *(__half2*)&f_sm[dd * FS2 + nf + j * 4    ] = __floats2half2_rn(v.x, v.y);
                *(__half2*)&f_sm[dd * FS2 + nf + j * 4 + 2] = __floats2half2_rn(v.z, v.w);
            }
        }
        __syncthreads();

        #pragma unroll
        for (int k16 = 0; k16 < 2; k16++) {
            const int co = k16 * 16;
            uint32_t A[2][4];
            #pragma unroll
            for (int mt = 0; mt < 2; mt++)
                ldsm4t(A[mt][0], A[mt][1], A[mt][2], A[mt][3],
                       fsb + ((co + lrow) * FS2 + Qn + mt * 16 + lcol) * 2);
            #pragma unroll
            for (int ct = 0; ct < 4; ct++) {
                uint32_t r0, r1, r2, r3;
                ldsm4(r0, r1, r2, r3,
                      wsb + ((Cw + ct * 16 + lrow) * WS2 + co + lcol) * 2);
                #pragma unroll
                for (int mt = 0; mt < 2; mt++) {
                    mma_f16(acc[mt][2 * ct    ], A[mt], r0, r1);
                    mma_f16(acc[mt][2 * ct + 1], A[mt], r2, r3);
                }
            }
        }
    }

    // ---- epilogues ----
    if (zi == 0) {          // theta: fp16 [n][c], pre-scaled by log2e
        #pragma unroll
        for (int mt = 0; mt < 2; mt++) {
            int n = n0 + Qn + mt * 16 + grp;
            #pragma unroll
            for (int nt = 0; nt < 8; nt++) {
                int c = Cw + nt * 8 + 2 * tig;
                float2 bb = *(const float2*)&bs[c];
                *(__half2*)&d_thh[((size_t)b * Nn + n) * CIc + c] =
                    __floats2half2_rn((acc[mt][nt][0] + bb.x) * LOG2E,
                                      (acc[mt][nt][1] + bb.y) * LOG2E);
                *(__half2*)&d_thh[((size_t)b * Nn + n + 8) * CIc + c] =
                    __floats2half2_rn((acc[mt][nt][2] + bb.x) * LOG2E,
                                      (acc[mt][nt][3] + bb.y) * LOG2E);
            }
        }
    } else if (zi == 1) {   // g: pool -> bf16 [m][c]
        #pragma unroll
        for (int mt = 0; mt < 2; mt++) {
            int mb = (n0 + Qn + mt * 16) >> 1;
            int m0 = mb + (grp >> 1), m1 = mb + 4 + (grp >> 1);
            #pragma unroll
            for (int nt = 0; nt < 8; nt++) {
                int c = Cw + nt * 8 + 2 * tig;
                float2 bb = *(const float2*)&bs[c];
                uint32_t u0 = packbf(acc[mt][nt][0] + bb.x, acc[mt][nt][1] + bb.y);
                uint32_t u1 = packbf(acc[mt][nt][2] + bb.x, acc[mt][nt][3] + bb.y);
                __nv_bfloat162 p0, p1, q0, q1;
                uint32_t o0 = shflx4(u0), o1 = shflx4(u1);
                p0 = *(__nv_bfloat162*)&u0; q0 = *(__nv_bfloat162*)&o0;
                p1 = *(__nv_bfloat162*)&u1; q1 = *(__nv_bfloat162*)&o1;
                __nv_bfloat162 h0 = __hmax2(p0, q0);
                __nv_bfloat162 h1 = __hmax2(p1, q1);
                if ((lane & 4) == 0) {
                    *(__nv_bfloat162*)&d_gbf[((size_t)b * Mm + m0) * CIc + c] = h0;
                    *(__nv_bfloat162*)&d_gbf[((size_t)b * Mm + m1) * CIc + c] = h1;
                }
            }
        }
    } else {                // phi: pool -> fp16 [m][c]
        #pragma unroll
        for (int mt = 0; mt < 2; mt++) {
            int mb = (n0 + Qn + mt * 16) >> 1;
            int m0 = mb + (grp >> 1), m1 = mb + 4 + (grp >> 1);
            #pragma unroll
            for (int nt = 0; nt < 8; nt++) {
                int c = Cw + nt * 8 + 2 * tig;
                float2 bb = *(const float2*)&bs[c];
                __half2 p0 = __floats2half2_rn(acc[mt][nt][0] + bb.x,
                                               acc[mt][nt][1] + bb.y);
                __half2 p1 = __floats2half2_rn(acc[mt][nt][2] + bb.x,
                                               acc[mt][nt][3] + bb.y);
                uint32_t u0 = *(uint32_t*)&p0, u1 = *(uint32_t*)&p1;
                uint32_t o0 = shflx4(u0), o1 = shflx4(u1);
                __half2 h0 = __hmax2(p0, *(__half2*)&o0);
                __half2 h1 = __hmax2(p1, *(__half2*)&o1);
                if ((lane & 4) == 0) {
                    *(__half2*)&d_phT[((size_t)b * Mm + m0) * CIc + c] = h0;
                    *(__half2*)&d_phT[((size_t)b * Mm + m1) * CIc + c] = h1;
                }
            }
        }
    }
}

// ============================================================================
// Kernel 2: sync-free tensor-core attention (all operands fp16/bf16 in gmem,
// pure cp.async staging). GEMM1 fp16 (theta pre-scaled, exp = ex2).
// GEMM2 bf16 with g [m][c] consumed via ldmatrix.trans.
// ============================================================================
#define SM_TH 0
#define SM_PH (128 * THH * 2)                 // 34816
#define SM_GG (SM_PH + 2 * 64 * PHH * 2)      // 69632
#define SM_ATTN (SM_GG + 2 * 64 * GH2 * 2)    // 104448

__global__ __launch_bounds__(256, 1) void attn_kernel()
{
    extern __shared__ char smc[];
    __half* th = (__half*)(smc + SM_TH);                 // [128 q][THH]
    const uint32_t smb = (uint32_t)__cvta_generic_to_shared(smc);

    const int b    = blockIdx.y;
    const int q0g  = blockIdx.x * 128;
    const int tid  = threadIdx.x;
    const int warp = tid >> 5;
    const int lane = tid & 31;
    const int grp  = lane >> 2;
    const int tig  = lane & 3;
    const int QB   = warp * 16;
    const int lrow = ((lane >> 4) << 3) + (lane & 7);
    const int lcol = ((lane >> 3) & 1) * 8;

    const __half*        thg = d_thh + ((size_t)b * Nn + q0g) * CIc;
    const __half*        phg = d_phT + (size_t)b * Mm * CIc;
    const __nv_bfloat16* ggm = d_gbf + (size_t)b * Mm * CIc;

    // ---- prefetch chunk 0 (phi+g) and theta tile, one commit ----
    #pragma unroll
    for (int r = 0; r < 4; r++) {
        int gI = tid + r * 256;
        int k = gI >> 4, off = (gI & 15) * 8;
        cp16(smb + SM_PH + (k * PHH + off) * 2, phg + (size_t)k * CIc + off);
        cp16(smb + SM_GG + (k * GH2 + off) * 2, ggm + (size_t)k * CIc + off);
    }
    #pragma unroll
    for (int r = 0; r < 8; r++) {
        int gI = tid + r * 256;
        int q = gI >> 4, off = (gI & 15) * 8;
        cp16(smb + SM_TH + (q * THH + off) * 2, thg + (size_t)q * CIc + off);
    }
    asm volatile("cp.async.commit_group;");
    asm volatile("cp.async.wait_group 0;");
    __syncthreads();

    // ---- cache all theta A-fragments: 8 k16 steps x 4 regs ----
    uint32_t Ac[8][4];
    #pragma unroll
    for (int c8 = 0; c8 < 8; c8++) {
        const int co = c8 * 16 + 2 * tig;
        Ac[c8][0] = *(const uint32_t*)&th[(QB + grp    ) * THH + co    ];
        Ac[c8][1] = *(const uint32_t*)&th[(QB + grp + 8) * THH + co    ];
        Ac[c8][2] = *(const uint32_t*)&th[(QB + grp    ) * THH + co + 8];
        Ac[c8][3] = *(const uint32_t*)&th[(QB + grp + 8) * THH + co + 8];
    }

    float yacc[16][4];
    #pragma unroll
    for (int nt = 0; nt < 16; nt++)
        #pragma unroll
        for (int r = 0; r < 4; r++) yacc[nt][r] = 0.f;
    float lsum0 = 0.f, lsum1 = 0.f;

    for (int ic = 0; ic < Mm / 64; ic++) {
        const int buf = ic & 1;
        asm volatile("cp.async.wait_group 0;");
        __syncthreads();

        if (ic + 1 < Mm / 64) {
            const int k0n = (ic + 1) * 64;
            const uint32_t phd = smb + SM_PH + (buf ^ 1) * 64 * PHH * 2;
            const uint32_t ggd = smb + SM_GG + (buf ^ 1) * 64 * GH2 * 2;
            const __half*        phs = phg + (size_t)k0n * CIc;
            const __nv_bfloat16* ggs = ggm + (size_t)k0n * CIc;
            #pragma unroll
            for (int r = 0; r < 4; r++) {
                int gI = tid + r * 256;
                int k = gI >> 4, off = (gI & 15) * 8;
                cp16(phd + (k * PHH + off) * 2, phs + (size_t)k * CIc + off);
                cp16(ggd + (k * GH2 + off) * 2, ggs + (size_t)k * CIc + off);
            }
            asm volatile("cp.async.commit_group;");
        }

        const uint32_t phb = smb + SM_PH + buf * 64 * PHH * 2;
        const uint32_t ggb = smb + SM_GG + buf * 64 * GH2 * 2;

        // ---- GEMM1: S[16q x 64k] (fp16, base-2 logits) ----
        float s[8][4];
        #pragma unroll
        for (int nt = 0; nt < 8; nt++)
            #pragma unroll
            for (int r = 0; r < 4; r++) s[nt][r] = 0.f;

        #pragma unroll
        for (int c8 = 0; c8 < 8; c8++) {
            #pragma unroll
            for (int ntp = 0; ntp < 4; ntp++) {
                uint32_t r0, r1, r2, r3;
                ldsm4(r0, r1, r2, r3,
                      phb + ((ntp * 16 + lrow) * PHH + c8 * 16 + lcol) * 2);
                mma_f16(s[2 * ntp    ], Ac[c8], r0, r1);
                mma_f16(s[2 * ntp + 1], Ac[c8], r2, r3);
            }
        }

        // ---- exp (ex2) in registers, pack bf16 A-frags, row sums ----
        #pragma unroll
        for (int nt = 0; nt < 8; nt++) {
            #pragma unroll
            for (int r = 0; r < 4; r++) s[nt][r] = ex2f(s[nt][r]);
            lsum0 += s[nt][0] + s[nt][1];
            lsum1 += s[nt][2] + s[nt][3];
        }
        uint32_t Pa[4][4];
        #pragma unroll
        for (int kk = 0; kk < 4; kk++) {
            Pa[kk][0] = packbf(s[2 * kk    ][0], s[2 * kk    ][1]);
            Pa[kk][1] = packbf(s[2 * kk    ][2], s[2 * kk    ][3]);
            Pa[kk][2] = packbf(s[2 * kk + 1][0], s[2 * kk + 1][1]);
            Pa[kk][3] = packbf(s[2 * kk + 1][2], s[2 * kk + 1][3]);
        }

        // ---- GEMM2: Y[16q x 128c] += P . g (bf16, g[m][c] via ldsm.trans) ----
        #pragma unroll
        for (int kk = 0; kk < 4; kk++) {
            #pragma unroll
            for (int ntp = 0; ntp < 8; ntp++) {
                uint32_t r0, r1, r2, r3;
                ldsm4t(r0, r1, r2, r3,
                       ggb + ((kk * 16 + lrow) * GH2 + ntp * 16 + lcol) * 2);
                mma_bf16(yacc[2 * ntp    ], Pa[kk], r0, r2);
                mma_bf16(yacc[2 * ntp + 1], Pa[kk], r1, r3);
            }
        }
    }

    // ---- normalize + store y as fp16 (B, N, CI) ----
    lsum0 += __shfl_xor_sync(0xffffffffu, lsum0, 1);
    lsum0 += __shfl_xor_sync(0xffffffffu, lsum0, 2);
    lsum1 += __shfl_xor_sync(0xffffffffu, lsum1, 1);
    lsum1 += __shfl_xor_sync(0xffffffffu, lsum1, 2);
    const float inv0 = 1.f / lsum0, inv1 = 1.f / lsum1;

    __half* yb0 = d_yh + ((size_t)b * Nn + q0g + QB + grp) * CIc;
    __half* yb1 = yb0 + 8 * CIc;
    #pragma unroll
    for (int nt = 0; nt < 16; nt++) {
        int c = nt * 8 + 2 * tig;
        *(__half2*)&yb0[c] = __floats2half2_rn(yacc[nt][0] * inv0,
                                               yacc[nt][1] * inv0);
        *(__half2*)&yb1[c] = __floats2half2_rn(yacc[nt][2] * inv1,
                                               yacc[nt][3] * inv1);
    }
}

// ============================================================================
// Kernel 3: W conv (fp16 mma, K=128 single pass) + BN partials (non-atomic).
// ============================================================================
#define SM_WCONV (2 * 128 * WWH * 2 + 2 * 128 * 8)   // 71680

__global__ __launch_bounds__(256) void wconv_tc(
    const float* __restrict__ Ww, const float* __restrict__ Wb)
{
    extern __shared__ char smc[];
    __half* wsm = (__half*)smc;                        // [128 d][WWH]
    double* shs = (double*)(smc + 2 * 128 * WWH * 2);  // [128]
    double* shq = shs + 128;                           // [128]
    const uint32_t smb = (uint32_t)__cvta_generic_to_shared(smc);
    const uint32_t ysb = smb + 128 * WWH * 2;

    const int b    = blockIdx.z;
    const int dblk = blockIdx.y * 128;
    const int n0   = blockIdx.x * 128;
    const int tid  = threadIdx.x;
    const int warp = tid >> 5;
    const int lane = tid & 31;
    const int grp  = lane >> 2;
    const int tig  = lane & 3;
    const int Dw   = (warp >> 1) * 32;
    const int Nw2  = (warp & 1) * 64;
    const int lrow = ((lane >> 4) << 3) + (lane & 7);
    const int lcol = ((lane >> 3) & 1) * 8;

    const __half* yh = d_yh + ((size_t)b * Nn + n0) * CIc;
    #pragma unroll
    for (int r = 0; r < 8; r++) {
        int gI = tid + r * 256;
        int n = gI >> 4, off = (gI & 15) * 8;
        cp16(ysb + (n * WWH + off) * 2, yh + (size_t)n * CIc + off);
    }
    asm volatile("cp.async.commit_group;");

    #pragma unroll
    for (int r = 0; r < 16; r++) {
        int fi = tid + r * 256;
        int dl = fi >> 5, c4 = (fi & 31) * 4;
        float4 v = *(const float4*)&Ww[(size_t)(dblk + dl) * CIc + c4];
        *(__half2*)&wsm[dl * WWH + c4    ] = __floats2half2_rn(v.x, v.y);
        *(__half2*)&wsm[dl * WWH + c4 + 2] = __floats2half2_rn(v.z, v.w);
    }
    if (tid < 128) { shs[tid] = 0.0; shq[tid] = 0.0; }
    asm volatile("cp.async.wait_group 0;");
    __syncthreads();

    float acc[2][8][4];
    #pragma unroll
    for (int mt = 0; mt < 2; mt++)
        #pragma unroll
        for (int nt = 0; nt < 8; nt++)
            #pragma unroll
            for (int r = 0; r < 4; r++) acc[mt][nt][r] = 0.f;

    #pragma unroll
    for (int k8 = 0; k8 < 8; k8++) {
        const int co = k8 * 16 + 2 * tig;
        uint32_t A[2][4];
        #pragma unroll
        for (int mt = 0; mt < 2; mt++) {
            int rb = Dw + mt * 16 + grp;
            A[mt][0] = *(const uint32_t*)&wsm[(rb    ) * WWH + co    ];
            A[mt][1] = *(const uint32_t*)&wsm[(rb + 8) * WWH + co    ];
            A[mt][2] = *(const uint32_t*)&wsm[(rb    ) * WWH + co + 8];
            A[mt][3] = *(const uint32_t*)&wsm[(rb + 8) * WWH + co + 8];
        }
        #pragma unroll
        for (int ntp = 0; ntp < 4; ntp++) {
            uint32_t r0, r1, r2, r3;
            ldsm4(r0, r1, r2, r3,
                  ysb + ((Nw2 + ntp * 16 + lrow) * WWH + k8 * 16 + lcol) * 2);
            mma_f16(acc[0][2 * ntp    ], A[0], r0, r1);
            mma_f16(acc[1][2 * ntp    ], A[1], r0, r1);
            mma_f16(acc[0][2 * ntp + 1], A[0], r2, r3);
            mma_f16(acc[1][2 * ntp + 1], A[1], r2, r3);
        }
    }

    // epilogue: bias + store Wy + BN partials
    #pragma unroll
    for (int mt = 0; mt < 2; mt++) {
        int d0 = dblk + Dw + mt * 16 + grp;
        float bias0 = Wb[d0], bias1 = Wb[d0 + 8];
        float s0 = 0.f, q0 = 0.f, s1 = 0.f, q1 = 0.f;
        #pragma unroll
        for (int nt = 0; nt < 8; nt++) {
            int n = n0 + Nw2 + nt * 8 + 2 * tig;
            float v0 = acc[mt][nt][0] + bias0, v1 = acc[mt][nt][1] + bias0;
            float v2 = acc[mt][nt][2] + bias1, v3 = acc[mt][nt][3] + bias1;
            *(float2*)&d_Wy[((size_t)b * Dd + d0) * Nn + n] = make_float2(v0, v1);
            *(float2*)&d_Wy[((size_t)b * Dd + d0 + 8) * Nn + n] = make_float2(v2, v3);
            s0 += v0 + v1;  q0 += v0 * v0 + v1 * v1;
            s1 += v2 + v3;  q1 += v2 * v2 + v3 * v3;
        }
        s0 += __shfl_xor_sync(0xffffffffu, s0, 1);
        s0 += __shfl_xor_sync(0xffffffffu, s0, 2);
        q0 += __shfl_xor_sync(0xffffffffu, q0, 1);
        q0 += __shfl_xor_sync(0xffffffffu, q0, 2);
        s1 += __shfl_xor_sync(0xffffffffu, s1, 1);
        s1 += __shfl_xor_sync(0xffffffffu, s1, 2);
        q1 += __shfl_xor_sync(0xffffffffu, q1, 1);
        q1 += __shfl_xor_sync(0xffffffffu, q1, 2);
        if (tig == 0) {
            int ld = Dw + mt * 16 + grp;
            atomicAdd(&shs[ld],     (double)s0);
            atomicAdd(&shq[ld],     (double)q0);
            atomicAdd(&shs[ld + 8], (double)s1);
            atomicAdd(&shq[ld + 8], (double)q1);
        }
    }
    __syncthreads();
    if (tid < 128) {   // non-atomic partial slot: column = nblk*2 + b
        int col = blockIdx.x * 2 + b;
        d_sum[(size_t)(dblk + tid) * 128 + col] = shs[tid];
        d_sq [(size_t)(dblk + tid) * 128 + col] = shq[tid];
    }
}

// ============================================================================
// Kernel 4: per-(b,d)-row finalize: reduce partials, BN + residual + output.
// grid (Dd, Bb), 256 threads; each block owns one 8192-float row.
// ============================================================================
__global__ __launch_bounds__(256) void final_kernel(
    const float* __restrict__ f, const float* __restrict__ gamma,
    const float* __restrict__ beta, float* __restrict__ out)
{
    __shared__ double sh[128], sq[128];
    __shared__ float gb2[2];
    const int d = blockIdx.x, b = blockIdx.y, tid = threadIdx.x;

    if (tid < 128) {
        sh[tid] = d_sum[(size_t)d * 128 + tid];
        sq[tid] = d_sq [(size_t)d * 128 + tid];
    }
    __syncthreads();
    for (int o = 64; o > 0; o >>= 1) {
        if (tid < o) { sh[tid] += sh[tid + o]; sq[tid] += sq[tid + o]; }
        __syncthreads();
    }
    if (tid == 0) {
        double cnt  = (double)(Bb * Nn);
        double mean = sh[0] / cnt;
        double var  = sq[0] / cnt - mean * mean;
        float inv = (float)(1.0 / sqrt(var + 1e-5));
        float gm = gamma[d] * inv;
        gb2[0] = gm;
        gb2[1] = beta[d] - (float)mean * gm;
    }
    __syncthreads();
    const float gm = gb2[0], bt = gb2[1];

    const float* wrow = d_Wy + ((size_t)b * Dd + d) * Nn;
    const float* frow = f    + ((size_t)b * Dd + d) * Nn;
    float*       orow = out  + ((size_t)b * Dd + d) * Nn;
    #pragma unroll
    for (int r = 0; r < 8; r++) {
        int i = (tid + r * 256) * 4;
        float4 w  = *(const float4*)&wrow[i];
        float4 fv = *(const float4*)&frow[i];
        float4 o;
        o.x = fmaf(w.x, gm, bt) + fv.x;
        o.y = fmaf(w.y, gm, bt) + fv.y;
        o.z = fmaf(w.z, gm, bt) + fv.z;
        o.w = fmaf(w.w, gm, bt) + fv.w;
        *(float4*)&orow[i] = o;
    }
}

// ============================================================================
extern "C" void kernel_launch(void* const* d_in, const int* in_sizes, int n_in,
                              void* d_out, int out_size)
{
    const float* f   = (const float*)d_in[0];
    const float* gw  = (const float*)d_in[1];
    const float* gb  = (const float*)d_in[2];
    const float* tw  = (const float*)d_in[3];
    const float* tb  = (const float*)d_in[4];
    const float* pw  = (const float*)d_in[5];
    const float* pb  = (const float*)d_in[6];
    const float* Ww  = (const float*)d_in[7];
    const float* Wb  = (const float*)d_in[8];
    const float* gma = (const float*)d_in[9];
    const float* bta = (const float*)d_in[10];
    float* out = (float*)d_out;

    static int attr_set = 0;
    if (!attr_set) {
        cudaFuncSetAttribute(attn_kernel,
                             cudaFuncAttributeMaxDynamicSharedMemorySize, SM_ATTN);
        cudaFuncSetAttribute(wconv_tc,
                             cudaFuncAttributeMaxDynamicSharedMemorySize, SM_WCONV);
        attr_set = 1;
    }

    proj_tc<<<dim3(Nn / 128, 3, Bb), 256>>>(f, gw, gb, tw, tb, pw, pb);
    attn_kernel<<<dim3(Nn / 128, Bb), 256, SM_ATTN>>>();
    wconv_tc<<<dim3(Nn / 128, Dd / 128, Bb), 256, SM_WCONV>>>(Ww, Wb);
    final_kernel<<<dim3(Dd, Bb), 256>>>(f, gma, bta, out);
}